// round 1
// baseline (speedup 1.0000x reference)
#include <cuda_runtime.h>
#include <math.h>

#define Nn   128
#define TCAP 31
#define T    30
#define CIN  1280
#define WD   512
#define HD   1024
#define VOC  10000
#define G4   4096   // 4*HD
#define P16  16

// ---------------- static device scratch (no runtime allocation) -------------
__device__ float g_Aflat[Nn * HD * P16];     // 8 MB   A_flat[n, h, p]
__device__ float g_h[Nn * HD];               // 0.5 MB
__device__ float g_c[Nn * HD];
__device__ float g_attn[Nn * HD];
__device__ float g_Xpre[Nn * T * G4];        // 63 MB  rows (n*T+t)
__device__ float g_gates[Nn * G4];           // 2 MB
__device__ float g_hs[T * Nn * HD];          // 15.7 MB rows (t*N+n)
__device__ float g_logits[(size_t)T * Nn * VOC]; // 153.6 MB

// ---------------------------------------------------------------------------
__global__ void zero_kernel(float* out) {
    if (threadIdx.x == 0) out[0] = 0.0f;
}

// ============================================================================
// 1) A_flat[n,h,p] = sum_c images[n,c,p] * W_proj[c,h] + b_proj[h]
//    GEMM: rows r=(n,p) in [0,2048), cols h in [0,1024), K=1280
// ============================================================================
__global__ void proj_kernel(const float* __restrict__ images,
                            const float* __restrict__ Wp,
                            const float* __restrict__ bp) {
    const int BM = 64, BN = 64, BK = 16;
    __shared__ float As[BK][BM + 1];
    __shared__ float Bs[BK][BN];
    int tid = threadIdx.x;
    int rowBase = blockIdx.y * BM;
    int colBase = blockIdx.x * BN;
    int ty = tid / 16, tx = tid % 16;
    float acc[4][4] = {};

    for (int k0 = 0; k0 < CIN; k0 += BK) {
#pragma unroll
        for (int i = 0; i < 4; i++) {
            int idx = tid + i * 256;
            int m = idx / BK, k = idx % BK;
            int row = rowBase + m;
            As[k][m] = images[(row >> 4) * (CIN * 16) + (k0 + k) * 16 + (row & 15)];
        }
#pragma unroll
        for (int i = 0; i < 4; i++) {
            int idx = tid + i * 256;
            int k = idx / BN, c = idx % BN;
            Bs[k][c] = Wp[(k0 + k) * HD + colBase + c];
        }
        __syncthreads();
#pragma unroll
        for (int k = 0; k < BK; k++) {
            float a[4], bb[4];
#pragma unroll
            for (int i = 0; i < 4; i++) a[i] = As[k][ty * 4 + i];
#pragma unroll
            for (int j = 0; j < 4; j++) bb[j] = Bs[k][tx * 4 + j];
#pragma unroll
            for (int i = 0; i < 4; i++)
#pragma unroll
                for (int j = 0; j < 4; j++) acc[i][j] += a[i] * bb[j];
        }
        __syncthreads();
    }
#pragma unroll
    for (int i = 0; i < 4; i++) {
        int row = rowBase + ty * 4 + i;
        int n = row >> 4, p = row & 15;
#pragma unroll
        for (int j = 0; j < 4; j++) {
            int h = colBase + tx * 4 + j;
            g_Aflat[n * (HD * 16) + h * 16 + p] = acc[i][j] + bp[h];
        }
    }
}

// h0 = c0 = mean over p of A_flat
__global__ void h0_kernel() {
    int idx = blockIdx.x * blockDim.x + threadIdx.x;
    if (idx < Nn * HD) {
        const float* a = &g_Aflat[idx * 16];
        float s = 0.f;
#pragma unroll
        for (int p = 0; p < 16; p++) s += a[p];
        s *= (1.0f / 16.0f);
        g_h[idx] = s;
        g_c[idx] = s;
    }
}

// ============================================================================
// 2) Xpre[(n*T+t), j] = W_embed[cap[n,t]] @ Wx + b   (rows 3840, cols 4096, K 512)
// ============================================================================
__global__ void xpre_kernel(const int* __restrict__ captions,
                            const float* __restrict__ W_embed,
                            const float* __restrict__ Wx,
                            const float* __restrict__ b) {
    const int BM = 64, BN = 64, BK = 16;
    __shared__ float As[BK][BM + 1];
    __shared__ float Bs[BK][BN];
    int tid = threadIdx.x;
    int rowBase = blockIdx.y * BM;
    int colBase = blockIdx.x * BN;
    int ty = tid / 16, tx = tid % 16;

    long aBase[4];
    int ak[4], am[4];
#pragma unroll
    for (int i = 0; i < 4; i++) {
        int idx = tid + i * 256;
        am[i] = idx / BK;
        ak[i] = idx % BK;
        int row = rowBase + am[i];
        int n = row / T, t = row % T;
        aBase[i] = (long)captions[n * TCAP + t] * WD;
    }

    float acc[4][4] = {};
    for (int k0 = 0; k0 < WD; k0 += BK) {
#pragma unroll
        for (int i = 0; i < 4; i++)
            As[ak[i]][am[i]] = W_embed[aBase[i] + k0 + ak[i]];
#pragma unroll
        for (int i = 0; i < 4; i++) {
            int idx = tid + i * 256;
            int k = idx / BN, c = idx % BN;
            Bs[k][c] = Wx[(k0 + k) * G4 + colBase + c];
        }
        __syncthreads();
#pragma unroll
        for (int k = 0; k < BK; k++) {
            float a[4], bb[4];
#pragma unroll
            for (int i = 0; i < 4; i++) a[i] = As[k][ty * 4 + i];
#pragma unroll
            for (int j = 0; j < 4; j++) bb[j] = Bs[k][tx * 4 + j];
#pragma unroll
            for (int i = 0; i < 4; i++)
#pragma unroll
                for (int j = 0; j < 4; j++) acc[i][j] += a[i] * bb[j];
        }
        __syncthreads();
    }
#pragma unroll
    for (int i = 0; i < 4; i++) {
        int row = rowBase + ty * 4 + i;
#pragma unroll
        for (int j = 0; j < 4; j++) {
            int col = colBase + tx * 4 + j;
            g_Xpre[(size_t)row * G4 + col] = acc[i][j] + b[col];
        }
    }
}

// ============================================================================
// 3a) attention: scores = (h . A_flat[:,:,p])/sqrt(H); softmax over 16; attn
// ============================================================================
__global__ void attn_kernel() {
    int n = blockIdx.x;
    __shared__ float sh_h[HD];
    __shared__ float sh_s[16];
    int tid = threadIdx.x;  // 512 threads = 16 warps

    for (int h = tid; h < HD; h += 512) sh_h[h] = g_h[n * HD + h];
    __syncthreads();

    int w = tid >> 5, lane = tid & 31;
    const float* A = &g_Aflat[n * HD * 16];
    float s = 0.f;
    for (int h = lane; h < HD; h += 32) s += sh_h[h] * A[h * 16 + w];
#pragma unroll
    for (int o = 16; o > 0; o >>= 1) s += __shfl_down_sync(0xffffffffu, s, o);
    if (lane == 0) sh_s[w] = s * 0.03125f;   // 1/sqrt(1024)
    __syncthreads();

    if (tid < 32) {
        float v = (lane < 16) ? sh_s[lane] : -INFINITY;
        float m = v;
#pragma unroll
        for (int o = 16; o > 0; o >>= 1) m = fmaxf(m, __shfl_xor_sync(0xffffffffu, m, o));
        float e = (lane < 16) ? __expf(v - m) : 0.f;
        float sum = e;
#pragma unroll
        for (int o = 16; o > 0; o >>= 1) sum += __shfl_xor_sync(0xffffffffu, sum, o);
        if (lane < 16) sh_s[lane] = e / sum;
    }
    __syncthreads();

    for (int h = tid; h < HD; h += 512) {
        const float* ap = &A[h * 16];
        float r = 0.f;
#pragma unroll
        for (int p = 0; p < 16; p++) r += ap[p] * sh_s[p];
        g_attn[n * HD + h] = r;
    }
}

// ============================================================================
// 3b) gates = Xpre[t] + h @ Wh + attn @ Wattn   (rows 128, cols 4096, K 2x1024)
// ============================================================================
__global__ void step_gemm(const float* __restrict__ Wh,
                          const float* __restrict__ Wattn, int t) {
    const int BM = 64, BN = 64, BK = 16;
    __shared__ float As[BK][BM + 1];
    __shared__ float Bs[BK][BN];
    int tid = threadIdx.x;
    int rowBase = blockIdx.y * BM;
    int colBase = blockIdx.x * BN;
    int ty = tid / 16, tx = tid % 16;
    float acc[4][4] = {};

    for (int ph = 0; ph < 2; ph++) {
        const float* Amat = ph ? g_attn : g_h;
        const float* Bmat = ph ? Wattn : Wh;
        for (int k0 = 0; k0 < HD; k0 += BK) {
#pragma unroll
            for (int i = 0; i < 4; i++) {
                int idx = tid + i * 256;
                int m = idx / BK, k = idx % BK;
                As[k][m] = Amat[(rowBase + m) * HD + k0 + k];
            }
#pragma unroll
            for (int i = 0; i < 4; i++) {
                int idx = tid + i * 256;
                int k = idx / BN, c = idx % BN;
                Bs[k][c] = Bmat[(k0 + k) * G4 + colBase + c];
            }
            __syncthreads();
#pragma unroll
            for (int k = 0; k < BK; k++) {
                float a[4], bb[4];
#pragma unroll
                for (int i = 0; i < 4; i++) a[i] = As[k][ty * 4 + i];
#pragma unroll
                for (int j = 0; j < 4; j++) bb[j] = Bs[k][tx * 4 + j];
#pragma unroll
                for (int i = 0; i < 4; i++)
#pragma unroll
                    for (int j = 0; j < 4; j++) acc[i][j] += a[i] * bb[j];
            }
            __syncthreads();
        }
    }
#pragma unroll
    for (int i = 0; i < 4; i++) {
        int n = rowBase + ty * 4 + i;
#pragma unroll
        for (int j = 0; j < 4; j++) {
            int col = colBase + tx * 4 + j;
            g_gates[n * G4 + col] = acc[i][j] + g_Xpre[((size_t)n * T + t) * G4 + col];
        }
    }
}

// 3c) LSTM elementwise update; writes h into time-major g_hs
__device__ __forceinline__ float sigf(float x) { return 1.0f / (1.0f + __expf(-x)); }

__global__ void lstm_kernel(int t) {
    int idx = blockIdx.x * blockDim.x + threadIdx.x;
    if (idx < Nn * HD) {
        int n = idx >> 10, h = idx & 1023;
        const float* gr = &g_gates[n * G4];
        float gi = gr[h], gf = gr[h + HD], go = gr[h + 2 * HD], gg = gr[h + 3 * HD];
        float c = sigf(gf) * g_c[idx] + sigf(gi) * tanhf(gg);
        float hh = sigf(go) * tanhf(c);
        g_c[idx] = c;
        g_h[idx] = hh;
        g_hs[((size_t)t * Nn + n) * HD + h] = hh;
    }
}

// ============================================================================
// 4) logits = hs @ W_vocab + b_vocab   (rows 3840, cols 10000, K 1024)
// ============================================================================
__global__ void logits_kernel(const float* __restrict__ Wv,
                              const float* __restrict__ bv) {
    const int BM = 64, BN = 64, BK = 16;
    __shared__ float As[BK][BM + 1];
    __shared__ float Bs[BK][BN];
    int tid = threadIdx.x;
    int rowBase = blockIdx.y * BM;
    int colBase = blockIdx.x * BN;
    int ty = tid / 16, tx = tid % 16;
    float acc[4][4] = {};

    for (int k0 = 0; k0 < HD; k0 += BK) {
#pragma unroll
        for (int i = 0; i < 4; i++) {
            int idx = tid + i * 256;
            int m = idx / BK, k = idx % BK;
            As[k][m] = g_hs[(size_t)(rowBase + m) * HD + k0 + k];
        }
#pragma unroll
        for (int i = 0; i < 4; i++) {
            int idx = tid + i * 256;
            int k = idx / BN, c = idx % BN;
            int col = colBase + c;
            Bs[k][c] = (col < VOC) ? Wv[(size_t)(k0 + k) * VOC + col] : 0.f;
        }
        __syncthreads();
#pragma unroll
        for (int k = 0; k < BK; k++) {
            float a[4], bb[4];
#pragma unroll
            for (int i = 0; i < 4; i++) a[i] = As[k][ty * 4 + i];
#pragma unroll
            for (int j = 0; j < 4; j++) bb[j] = Bs[k][tx * 4 + j];
#pragma unroll
            for (int i = 0; i < 4; i++)
#pragma unroll
                for (int j = 0; j < 4; j++) acc[i][j] += a[i] * bb[j];
        }
        __syncthreads();
    }
#pragma unroll
    for (int i = 0; i < 4; i++) {
        int row = rowBase + ty * 4 + i;
#pragma unroll
        for (int j = 0; j < 4; j++) {
            int col = colBase + tx * 4 + j;
            if (col < VOC)
                g_logits[(size_t)row * VOC + col] = acc[i][j] + bv[col];
        }
    }
}

// 5) per-row logsumexp + masked NLL, accumulated into out[0]
__global__ void loss_kernel(const int* __restrict__ captions, float* out) {
    int r = blockIdx.x;               // r = t*N + n
    __shared__ float red[256];
    const float* row = &g_logits[(size_t)r * VOC];
    int tid = threadIdx.x;

    float m = -INFINITY;
    for (int v = tid; v < VOC; v += 256) m = fmaxf(m, row[v]);
    red[tid] = m;
    __syncthreads();
    for (int s = 128; s > 0; s >>= 1) {
        if (tid < s) red[tid] = fmaxf(red[tid], red[tid + s]);
        __syncthreads();
    }
    float mx = red[0];
    __syncthreads();

    float se = 0.f;
    for (int v = tid; v < VOC; v += 256) se += expf(row[v] - mx);
    red[tid] = se;
    __syncthreads();
    for (int s = 128; s > 0; s >>= 1) {
        if (tid < s) red[tid] += red[tid + s];
        __syncthreads();
    }

    if (tid == 0) {
        int t = r / Nn, n = r % Nn;
        int tgt = captions[n * TCAP + t + 1];
        if (tgt != 0) {
            float nll = logf(red[0]) + mx - row[tgt];
            atomicAdd(out, nll * (1.0f / Nn));
        }
    }
}

// ============================================================================
extern "C" void kernel_launch(void* const* d_in, const int* in_sizes, int n_in,
                              void* d_out, int out_size) {
    const float* images   = (const float*)d_in[0];
    const int*   captions = (const int*)  d_in[1];
    const float* W_embed  = (const float*)d_in[2];
    const float* W_proj   = (const float*)d_in[3];
    const float* b_proj   = (const float*)d_in[4];
    const float* Wx       = (const float*)d_in[5];
    const float* Wh       = (const float*)d_in[6];
    const float* Wattn    = (const float*)d_in[7];
    const float* b        = (const float*)d_in[8];
    const float* W_vocab  = (const float*)d_in[9];
    const float* b_vocab  = (const float*)d_in[10];
    float* out = (float*)d_out;

    zero_kernel<<<1, 32>>>(out);
    proj_kernel<<<dim3(HD / 64, 2048 / 64), 256>>>(images, W_proj, b_proj);
    h0_kernel<<<(Nn * HD) / 256, 256>>>();
    xpre_kernel<<<dim3(G4 / 64, (Nn * T) / 64), 256>>>(captions, W_embed, Wx, b);

    for (int t = 0; t < T; t++) {
        attn_kernel<<<Nn, 512>>>();
        step_gemm<<<dim3(G4 / 64, Nn / 64), 256>>>(Wh, Wattn, t);
        lstm_kernel<<<(Nn * HD) / 256, 256>>>(t);
    }

    logits_kernel<<<dim3((VOC + 63) / 64, (Nn * T) / 64), 256>>>(W_vocab, b_vocab);
    loss_kernel<<<T * Nn, 256>>>(captions, out);
}

// round 4
// speedup vs baseline: 1.6921x; 1.6921x over previous
#include <cuda_runtime.h>
#include <math.h>
#include <stdint.h>

#define Nn   128
#define TCAP 31
#define T    30
#define CIN  1280
#define WD   512
#define HD   1024
#define VOC  10000
#define G4   4096   // 4*HD

// ---------------- static device scratch (no runtime allocation) -------------
__device__ float g_Aflat[Nn * HD * 16];      // A_flat[n, h, p]
__device__ float g_h[Nn * HD];
__device__ float g_c[Nn * HD];
__device__ float g_attn[Nn * HD];
__device__ float g_Xpre[(size_t)Nn * T * G4];        // rows (n*T+t)
__device__ float g_gates[Nn * G4];
__device__ float g_hs[(size_t)T * Nn * HD];          // rows (t*N+n)
__device__ float g_logits[(size_t)T * Nn * VOC];

// ---------------------------------------------------------------------------
__global__ void zero_kernel(float* out) {
    if (threadIdx.x == 0) out[0] = 0.0f;
}

__device__ __forceinline__ uint32_t f2tf32(float f) {
    uint32_t u;
    asm("cvt.rna.tf32.f32 %0, %1;" : "=r"(u) : "f"(f));
    return u;
}

__device__ __forceinline__ void mma_tf32(float c[4], const uint32_t a[4], const uint32_t b[2]) {
    asm volatile(
        "mma.sync.aligned.m16n8k8.row.col.f32.tf32.tf32.f32 "
        "{%0,%1,%2,%3}, {%4,%5,%6,%7}, {%8,%9}, {%0,%1,%2,%3};"
        : "+f"(c[0]), "+f"(c[1]), "+f"(c[2]), "+f"(c[3])
        : "r"(a[0]), "r"(a[1]), "r"(a[2]), "r"(a[3]), "r"(b[0]), "r"(b[1]));
}

// ============================================================================
// Generic tf32 tensor-core GEMM, BM=128 BN=64 BK=16, 256 threads (8 warps),
// with register-prefetch software pipeline on global loads.
// MODE 0: Xpre  = gather(W_embed,cap) @ Wx + b        (M=3840, N=4096, K=512)
// MODE 1: logits = hs @ W_vocab + b_vocab             (M=3840, N=10000, K=1024)
// MODE 2: gates = [h|attn] @ [Wh;Wattn] + Xpre[:,t]   (M=128,  N=4096, K=2048)
// ============================================================================
template<int MODE>
__global__ void __launch_bounds__(256)
mma_gemm_kernel(const float* __restrict__ W_A,   // mode0: W_embed
                const float* __restrict__ W_B,   // Wx / W_vocab / Wh
                const float* __restrict__ W_B2,  // mode2: Wattn
                const float* __restrict__ bias,  // b / b_vocab / null
                const int*   __restrict__ captions,
                int tstep) {
    constexpr int BM = 128, BN = 64, BK = 16;
    constexpr int KDIM = (MODE == 0) ? WD : (MODE == 1 ? HD : 2 * HD);
    constexpr int NDIM = (MODE == 1) ? VOC : G4;

    __shared__ uint32_t As[BK][BM + 8];   // [k][row], stride 136 (mod 32 == 8) -> conflict-free frags
    __shared__ uint32_t Bs[BK][BN + 8];   // [k][col], stride 72

    const int tid  = threadIdx.x;
    const int rowBase = blockIdx.y * BM;
    const int colBase = blockIdx.x * BN;

    const int wid = tid >> 5, lane = tid & 31;
    const int gid = lane >> 2, tig = lane & 3;
    const int wr = wid & 3, wc = wid >> 2;      // warp tile 32x32 in 4x2 grid

    // A-load assignment: thread loads 8 consecutive k of one row
    const int arow = tid >> 1;
    const int kh   = (tid & 1) * 8;
    const float* aRow = nullptr;
    if (MODE == 0) {
        int row = rowBase + arow;
        int n = row / T, tt = row % T;
        aRow = W_A + (size_t)captions[n * TCAP + tt] * WD;
    } else if (MODE == 1) {
        aRow = g_hs + (size_t)(rowBase + arow) * HD;
    }
    // B-load assignment: thread loads 4 consecutive cols of one k
    const int bk = tid >> 4;
    const int bc = (tid & 15) * 4;

    float av[8];
    float bv[4];

    // prefetch helpers -------------------------------------------------------
    auto loadA = [&](int k0) {
        const float* src;
        if (MODE == 2) {
            int kg = k0 + kh;
            src = (kg < HD) ? &g_h[arow * HD + kg] : &g_attn[arow * HD + (kg - HD)];
        } else {
            src = aRow + k0 + kh;
        }
        float4 v0 = *(const float4*)(src);
        float4 v1 = *(const float4*)(src + 4);
        av[0] = v0.x; av[1] = v0.y; av[2] = v0.z; av[3] = v0.w;
        av[4] = v1.x; av[5] = v1.y; av[6] = v1.z; av[7] = v1.w;
    };
    auto loadB = [&](int k0) {
        const float* bsrc;
        if (MODE == 2) {
            int kg = k0 + bk;
            bsrc = (kg < HD) ? W_B  + (size_t)kg * NDIM + colBase + bc
                             : W_B2 + (size_t)(kg - HD) * NDIM + colBase + bc;
        } else {
            bsrc = W_B + (size_t)(k0 + bk) * NDIM + colBase + bc;
        }
        if (MODE == 1 && colBase + BN > NDIM) {
#pragma unroll
            for (int i = 0; i < 4; i++)
                bv[i] = (colBase + bc + i < NDIM) ? bsrc[i] : 0.f;
        } else {
            float4 v = *(const float4*)bsrc;
            bv[0] = v.x; bv[1] = v.y; bv[2] = v.z; bv[3] = v.w;
        }
    };

    float c[2][4][4] = {};

    loadA(0);
    loadB(0);

    for (int k0 = 0; k0 < KDIM; k0 += BK) {
        // commit prefetched tile to smem (with tf32 conversion)
#pragma unroll
        for (int i = 0; i < 8; i++) As[kh + i][arow] = f2tf32(av[i]);
#pragma unroll
        for (int i = 0; i < 4; i++) Bs[bk][bc + i] = f2tf32(bv[i]);
        __syncthreads();

        // issue next tile's global loads before compute (latency overlap)
        if (k0 + BK < KDIM) {
            loadA(k0 + BK);
            loadB(k0 + BK);
        }

        // ---- compute: 2 k-steps of 8 ----
#pragma unroll
        for (int ks = 0; ks < BK; ks += 8) {
            uint32_t a[2][4];
#pragma unroll
            for (int mt = 0; mt < 2; mt++) {
                int rA = wr * 32 + mt * 16 + gid;
                a[mt][0] = As[ks + tig][rA];
                a[mt][1] = As[ks + tig][rA + 8];
                a[mt][2] = As[ks + tig + 4][rA];
                a[mt][3] = As[ks + tig + 4][rA + 8];
            }
            uint32_t bfr[4][2];
#pragma unroll
            for (int nt = 0; nt < 4; nt++) {
                int cB = wc * 32 + nt * 8 + gid;
                bfr[nt][0] = Bs[ks + tig][cB];
                bfr[nt][1] = Bs[ks + tig + 4][cB];
            }
#pragma unroll
            for (int mt = 0; mt < 2; mt++)
#pragma unroll
                for (int nt = 0; nt < 4; nt++)
                    mma_tf32(c[mt][nt], a[mt], bfr[nt]);
        }
        __syncthreads();
    }

    // ---- epilogue ----
#pragma unroll
    for (int mt = 0; mt < 2; mt++) {
        int r0 = rowBase + wr * 32 + mt * 16 + gid;
#pragma unroll
        for (int nt = 0; nt < 4; nt++) {
            int col = colBase + wc * 32 + nt * 8 + tig * 2;
            if (MODE == 0) {
                size_t o0 = (size_t)r0 * G4 + col;
                size_t o1 = (size_t)(r0 + 8) * G4 + col;
                float b0 = bias[col], b1 = bias[col + 1];
                g_Xpre[o0]     = c[mt][nt][0] + b0;
                g_Xpre[o0 + 1] = c[mt][nt][1] + b1;
                g_Xpre[o1]     = c[mt][nt][2] + b0;
                g_Xpre[o1 + 1] = c[mt][nt][3] + b1;
            } else if (MODE == 1) {
                if (col < VOC) {
                    float b0 = bias[col];
                    g_logits[(size_t)r0 * VOC + col]       = c[mt][nt][0] + b0;
                    g_logits[(size_t)(r0 + 8) * VOC + col] = c[mt][nt][2] + b0;
                }
                if (col + 1 < VOC) {
                    float b1 = bias[col + 1];
                    g_logits[(size_t)r0 * VOC + col + 1]       = c[mt][nt][1] + b1;
                    g_logits[(size_t)(r0 + 8) * VOC + col + 1] = c[mt][nt][3] + b1;
                }
            } else {
                size_t x0 = ((size_t)r0 * T + tstep) * G4 + col;
                size_t x1 = ((size_t)(r0 + 8) * T + tstep) * G4 + col;
                g_gates[r0 * G4 + col]           = c[mt][nt][0] + g_Xpre[x0];
                g_gates[r0 * G4 + col + 1]       = c[mt][nt][1] + g_Xpre[x0 + 1];
                g_gates[(r0 + 8) * G4 + col]     = c[mt][nt][2] + g_Xpre[x1];
                g_gates[(r0 + 8) * G4 + col + 1] = c[mt][nt][3] + g_Xpre[x1 + 1];
            }
        }
    }
}

// ============================================================================
// 1) A_flat[n,h,p] = sum_c images[n,c,p] * W_proj[c,h] + b_proj[h]  (SIMT)
// ============================================================================
__global__ void proj_kernel(const float* __restrict__ images,
                            const float* __restrict__ Wp,
                            const float* __restrict__ bp) {
    const int BM = 64, BN = 64, BK = 16;
    __shared__ float As[BK][BM + 1];
    __shared__ float Bs[BK][BN];
    int tid = threadIdx.x;
    int rowBase = blockIdx.y * BM;
    int colBase = blockIdx.x * BN;
    int ty = tid / 16, tx = tid % 16;
    float acc[4][4] = {};

    for (int k0 = 0; k0 < CIN; k0 += BK) {
#pragma unroll
        for (int i = 0; i < 4; i++) {
            int idx = tid + i * 256;
            int m = idx / BK, k = idx % BK;
            int row = rowBase + m;
            As[k][m] = images[(row >> 4) * (CIN * 16) + (k0 + k) * 16 + (row & 15)];
        }
#pragma unroll
        for (int i = 0; i < 4; i++) {
            int idx = tid + i * 256;
            int k = idx / BN, cc = idx % BN;
            Bs[k][cc] = Wp[(k0 + k) * HD + colBase + cc];
        }
        __syncthreads();
#pragma unroll
        for (int k = 0; k < BK; k++) {
            float a[4], bb[4];
#pragma unroll
            for (int i = 0; i < 4; i++) a[i] = As[k][ty * 4 + i];
#pragma unroll
            for (int j = 0; j < 4; j++) bb[j] = Bs[k][tx * 4 + j];
#pragma unroll
            for (int i = 0; i < 4; i++)
#pragma unroll
                for (int j = 0; j < 4; j++) acc[i][j] += a[i] * bb[j];
        }
        __syncthreads();
    }
#pragma unroll
    for (int i = 0; i < 4; i++) {
        int row = rowBase + ty * 4 + i;
        int n = row >> 4, p = row & 15;
#pragma unroll
        for (int j = 0; j < 4; j++) {
            int h = colBase + tx * 4 + j;
            g_Aflat[n * (HD * 16) + h * 16 + p] = acc[i][j] + bp[h];
        }
    }
}

// ============================================================================
// attention body: run by a full 1024-thread block with h in shared memory.
// Computes softmax((h . A_flat[:, :, p]) / sqrt(H)) and attn = A_flat @ w.
// ============================================================================
__device__ __forceinline__ void attn_body(int n, const float* sh_h, float* sh_s, int tid) {
    int w = tid >> 5, lane = tid & 31;
    const float* A = &g_Aflat[n * HD * 16];
    if (w < 16) {
        float s = 0.f;
        for (int h = lane; h < HD; h += 32) s += sh_h[h] * A[h * 16 + w];
#pragma unroll
        for (int o = 16; o > 0; o >>= 1) s += __shfl_down_sync(0xffffffffu, s, o);
        if (lane == 0) sh_s[w] = s * 0.03125f;   // 1/sqrt(1024)
    }
    __syncthreads();
    if (tid < 32) {
        float v = (lane < 16) ? sh_s[lane] : -INFINITY;
        float m = v;
#pragma unroll
        for (int o = 16; o > 0; o >>= 1) m = fmaxf(m, __shfl_xor_sync(0xffffffffu, m, o));
        float e = (lane < 16) ? __expf(v - m) : 0.f;
        float sum = e;
#pragma unroll
        for (int o = 16; o > 0; o >>= 1) sum += __shfl_xor_sync(0xffffffffu, sum, o);
        if (lane < 16) sh_s[lane] = e / sum;
    }
    __syncthreads();
    const float* ap = &A[tid * 16];
    float r = 0.f;
#pragma unroll
    for (int p = 0; p < 16; p++) r += ap[p] * sh_s[p];
    g_attn[n * HD + tid] = r;
}

// h0 = c0 = mean over p of A_flat, then attention for step 0. Block = sample n.
__global__ void h0_attn_kernel() {
    int n = blockIdx.x;
    int tid = threadIdx.x;   // 1024
    __shared__ float sh_h[HD];
    __shared__ float sh_s[16];
    const float* a = &g_Aflat[(n * HD + tid) * 16];
    float s = 0.f;
#pragma unroll
    for (int p = 0; p < 16; p++) s += a[p];
    s *= (1.0f / 16.0f);
    g_h[n * HD + tid] = s;
    g_c[n * HD + tid] = s;
    sh_h[tid] = s;
    __syncthreads();
    attn_body(n, sh_h, sh_s, tid);
}

// LSTM elementwise update fused with next step's attention. Block = sample n.
__device__ __forceinline__ float sigf(float x) { return 1.0f / (1.0f + __expf(-x)); }

__global__ void lstm_attn_kernel(int t, int doAttn) {
    int n = blockIdx.x;
    int tid = threadIdx.x;   // 1024
    __shared__ float sh_h[HD];
    __shared__ float sh_s[16];

    const float* gr = &g_gates[n * G4];
    float gi = gr[tid], gf = gr[tid + HD], go = gr[tid + 2 * HD], gg = gr[tid + 3 * HD];
    float c = sigf(gf) * g_c[n * HD + tid] + sigf(gi) * tanhf(gg);
    float hh = sigf(go) * tanhf(c);
    g_c[n * HD + tid] = c;
    g_h[n * HD + tid] = hh;
    g_hs[((size_t)t * Nn + n) * HD + tid] = hh;

    if (doAttn) {      // uniform branch across the block
        sh_h[tid] = hh;
        __syncthreads();
        attn_body(n, sh_h, sh_s, tid);
    }
}

// loss: per-row logsumexp + masked NLL accumulated into out[0]
__global__ void loss_kernel(const int* __restrict__ captions, float* out) {
    int r = blockIdx.x;               // r = t*N + n
    __shared__ float red[256];
    const float* row = &g_logits[(size_t)r * VOC];
    int tid = threadIdx.x;

    float m = -INFINITY;
    for (int v = tid; v < VOC; v += 256) m = fmaxf(m, row[v]);
    red[tid] = m;
    __syncthreads();
    for (int s = 128; s > 0; s >>= 1) {
        if (tid < s) red[tid] = fmaxf(red[tid], red[tid + s]);
        __syncthreads();
    }
    float mx = red[0];
    __syncthreads();

    float se = 0.f;
    for (int v = tid; v < VOC; v += 256) se += expf(row[v] - mx);
    red[tid] = se;
    __syncthreads();
    for (int s = 128; s > 0; s >>= 1) {
        if (tid < s) red[tid] += red[tid + s];
        __syncthreads();
    }

    if (tid == 0) {
        int t = r / Nn, n = r % Nn;
        int tgt = captions[n * TCAP + t + 1];
        if (tgt != 0) {
            float nll = logf(red[0]) + mx - row[tgt];
            atomicAdd(out, nll * (1.0f / Nn));
        }
    }
}

// ============================================================================
extern "C" void kernel_launch(void* const* d_in, const int* in_sizes, int n_in,
                              void* d_out, int out_size) {
    const float* images   = (const float*)d_in[0];
    const int*   captions = (const int*)  d_in[1];
    const float* W_embed  = (const float*)d_in[2];
    const float* W_proj   = (const float*)d_in[3];
    const float* b_proj   = (const float*)d_in[4];
    const float* Wx       = (const float*)d_in[5];
    const float* Wh       = (const float*)d_in[6];
    const float* Wattn    = (const float*)d_in[7];
    const float* b        = (const float*)d_in[8];
    const float* W_vocab  = (const float*)d_in[9];
    const float* b_vocab  = (const float*)d_in[10];
    float* out = (float*)d_out;

    zero_kernel<<<1, 32>>>(out);
    proj_kernel<<<dim3(HD / 64, 2048 / 64), 256>>>(images, W_proj, b_proj);
    h0_attn_kernel<<<Nn, 1024>>>();
    // Xpre: M=3840 rows (n*T+t), N=4096, K=512
    mma_gemm_kernel<0><<<dim3(G4 / 64, (Nn * T) / 128), 256>>>(
        W_embed, Wx, nullptr, b, captions, 0);

    for (int t = 0; t < T; t++) {
        mma_gemm_kernel<2><<<dim3(G4 / 64, 1), 256>>>(
            nullptr, Wh, Wattn, nullptr, nullptr, t);
        lstm_attn_kernel<<<Nn, 1024>>>(t, t < T - 1);
    }

    // logits: M=3840 (t*N+n), N=10000, K=1024
    mma_gemm_kernel<1><<<dim3((VOC + 63) / 64, (Nn * T) / 128), 256>>>(
        nullptr, W_vocab, nullptr, b_vocab, nullptr, 0);
    loss_kernel<<<T * Nn, 256>>>(captions, out);
}

// round 6
// speedup vs baseline: 2.2712x; 1.3422x over previous
#include <cuda_runtime.h>
#include <math.h>
#include <stdint.h>

#define Nn   128
#define TCAP 31
#define T    30
#define CIN  1280
#define WD   512
#define HD   1024
#define VOC  10000
#define G4   4096   // 4*HD

// ---------------- static device scratch (no runtime allocation) -------------
// tf32-converted weight copies (converted once per launch)
__device__ __align__(16) float g_embT[VOC * WD];          // 20.5 MB
__device__ __align__(16) float g_WxT[WD * G4];            // 8.4 MB
__device__ __align__(16) float g_WhA[2 * HD * G4];        // 33.5 MB  [Wh; Wattn]
__device__ __align__(16) float g_WvT[(size_t)HD * VOC];   // 40 MB
__device__ __align__(16) float g_WpT[CIN * HD];           // 5.2 MB
__device__ __align__(16) float g_imgT[2048 * CIN];        // 10.5 MB  images transposed, tf32
// activations
__device__ __align__(16) float g_hA[Nn * 2 * HD];         // [h | attn] tf32 per sample
__device__ __align__(16) float g_hsT[(size_t)T * Nn * HD];// tf32, rows (t*N+n)
__device__ float g_c[Nn * HD];
__device__ float g_Aflat[Nn * HD * 16];                   // fp32 A_flat[n,h,p]
__device__ __align__(16) float g_Xpre[(size_t)Nn * T * G4]; // fp32 rows (n*T+t)
__device__ float g_gates[Nn * G4];
__device__ float g_logits[(size_t)T * Nn * VOC];

// ---------------------------------------------------------------------------
__global__ void zero_kernel(float* out) {
    if (threadIdx.x == 0) out[0] = 0.0f;
}

__device__ __forceinline__ uint32_t f2tf32(float f) {
    uint32_t u;
    asm("cvt.rna.tf32.f32 %0, %1;" : "=r"(u) : "f"(f));
    return u;
}
__device__ __forceinline__ float tfv(float f) { return __uint_as_float(f2tf32(f)); }

__device__ __forceinline__ void mma_tf32(float c[4], const uint32_t a[4], const uint32_t b[2]) {
    asm volatile(
        "mma.sync.aligned.m16n8k8.row.col.f32.tf32.tf32.f32 "
        "{%0,%1,%2,%3}, {%4,%5,%6,%7}, {%8,%9}, {%0,%1,%2,%3};"
        : "+f"(c[0]), "+f"(c[1]), "+f"(c[2]), "+f"(c[3])
        : "r"(a[0]), "r"(a[1]), "r"(a[2]), "r"(a[3]), "r"(b[0]), "r"(b[1]));
}

__device__ __forceinline__ uint32_t smaddr(const void* p) {
    return (uint32_t)__cvta_generic_to_shared(p);
}
__device__ __forceinline__ void cpa16(uint32_t d, const void* s, int sz) {
    asm volatile("cp.async.cg.shared.global [%0], [%1], 16, %2;" :: "r"(d), "l"(s), "r"(sz));
}

// ============================================================================
// One-time per-launch weight conversion fp32 -> tf32 bits
// ============================================================================
#define N_EMB  (VOC * WD)
#define N_WX   (WD * G4)
#define N_WH   (HD * G4)
#define N_WV   (HD * VOC)
#define N_WP   (CIN * HD)
#define N_CVT  (N_EMB + N_WX + 2 * N_WH + N_WV + N_WP)

__global__ void cvt_weights(const float* __restrict__ We, const float* __restrict__ Wx,
                            const float* __restrict__ Wh, const float* __restrict__ Wa,
                            const float* __restrict__ Wv, const float* __restrict__ Wp) {
    int i = blockIdx.x * blockDim.x + threadIdx.x;
    if (i >= N_CVT) return;
    if (i < N_EMB) { g_embT[i] = tfv(We[i]); return; }
    i -= N_EMB;
    if (i < N_WX) { g_WxT[i] = tfv(Wx[i]); return; }
    i -= N_WX;
    if (i < N_WH) { g_WhA[i] = tfv(Wh[i]); return; }
    i -= N_WH;
    if (i < N_WH) { g_WhA[N_WH + i] = tfv(Wa[i]); return; }
    i -= N_WH;
    if (i < N_WV) { g_WvT[i] = tfv(Wv[i]); return; }
    i -= N_WV;
    g_WpT[i] = tfv(Wp[i]);
}

// images [n, c, p] -> imgT [(n*16+p), c] tf32, smem-tiled transpose. Block = n.
__global__ void imgT_kernel(const float* __restrict__ img) {
    __shared__ float tile[256][17];
    int n = blockIdx.x;
    for (int c0 = 0; c0 < CIN; c0 += 256) {
        for (int idx = threadIdx.x; idx < 256 * 16; idx += blockDim.x) {
            int cc = idx >> 4, p = idx & 15;
            tile[cc][p] = img[(size_t)n * CIN * 16 + (c0 + cc) * 16 + p];
        }
        __syncthreads();
        for (int idx = threadIdx.x; idx < 256 * 16; idx += blockDim.x) {
            int p = idx >> 8, cc = idx & 255;
            g_imgT[(size_t)(n * 16 + p) * CIN + c0 + cc] = tfv(tile[cc][p]);
        }
        __syncthreads();
    }
}

// ============================================================================
// tf32 tensor-core GEMM with cp.async 3-stage pipeline. BM=128, BK=16,
// BN=64 (modes 0,1,3) or BN=32 (mode 2). 256 threads = 8 warps.
// MODE 0: Xpre   = gather(embT,cap) @ WxT + b       (3840 x 4096, K=512)
// MODE 1: logits = hsT @ WvT + b_vocab              (3840 x 10000, K=1024)
// MODE 2: gates  = hA @ WhA + Xpre[:,t]             (128 x 4096, K=2048)
// MODE 3: Aflat  = imgT @ WpT + b_proj (scatter)    (2048 x 1024, K=1280)
// All A/B operands are pre-converted tf32 bits; no cvt in the inner loop.
// ============================================================================
template<int MODE>
__global__ void __launch_bounds__(256)
gemm_tc(const float* __restrict__ bias, const int* __restrict__ captions, int tstep) {
    constexpr int BM = 128, BK = 16;
    constexpr int BN  = (MODE == 2) ? 32 : 64;
    constexpr int NT  = BN / 16;          // n-tiles per warp
    constexpr int WCW = BN / 2;           // warp column width
    constexpr int KD  = (MODE == 0) ? WD : (MODE == 1) ? HD : (MODE == 2) ? 2 * HD : CIN;
    constexpr int LDB = (MODE == 1) ? VOC : (MODE == 3) ? HD : G4;
    constexpr int NIT = KD / BK;
    constexpr int AS = 20, BS = BN + 8;

    __shared__ __align__(16) float As[3][BM][AS];
    __shared__ __align__(16) float Bs[3][BK][BS];

    const float* Ab = (MODE == 0) ? g_embT : (MODE == 1) ? g_hsT :
                      (MODE == 2) ? g_hA   : g_imgT;
    const float* Bb = (MODE == 0) ? g_WxT  : (MODE == 1) ? g_WvT :
                      (MODE == 2) ? g_WhA  : g_WpT;

    const int tid = threadIdx.x;
    const int rowBase = blockIdx.y * BM;
    const int colBase = blockIdx.x * BN;
    const int wid = tid >> 5, lane = tid & 31;
    const int gid = lane >> 2, tig = lane & 3;
    const int wr = wid & 3, wc = wid >> 2;

    // A loads: thread handles 8 consecutive k of one row (2 x cp16)
    const int ar = tid >> 1, ak = (tid & 1) * 8;
    const float* aRow;
    if (MODE == 0) {
        int r = rowBase + ar;
        aRow = Ab + (size_t)captions[(r / T) * TCAP + (r % T)] * WD;
    } else {
        aRow = Ab + (size_t)(rowBase + ar) * KD;   // LDA == KD for modes 1,2,3
    }
    // B loads
    const int bk = (BN == 64) ? (tid >> 4) : (tid >> 3);
    const int bc = (BN == 64) ? ((tid & 15) * 4) : ((tid & 7) * 4);
    const bool bact = (BN == 64) || (tid < 128);

    auto issue = [&](int it) {
        int st = it % 3;
        int k0 = it * BK;
        uint32_t ad = smaddr(&As[st][ar][ak]);
        const float* as = aRow + k0 + ak;
        cpa16(ad, as, 16);
        cpa16(ad + 16, as + 4, 16);
        if (bact) {
            uint32_t bd = smaddr(&Bs[st][bk][bc]);
            const float* bs = Bb + (size_t)(k0 + bk) * LDB + colBase + bc;
            int sz = (MODE == 1 && colBase + bc + 4 > VOC) ? 0 : 16;
            cpa16(bd, bs, sz);
        }
        asm volatile("cp.async.commit_group;");
    };

    float c[2][NT][4] = {};

    issue(0);
    issue(1);

    for (int it = 0; it < NIT; ++it) {
        asm volatile("cp.async.wait_group 1;");
        __syncthreads();
        if (it + 2 < NIT) issue(it + 2);
        int st = it % 3;
#pragma unroll
        for (int ks = 0; ks < BK; ks += 8) {
            uint32_t a[2][4];
#pragma unroll
            for (int mt = 0; mt < 2; mt++) {
                int rA = wr * 32 + mt * 16 + gid;
                a[mt][0] = __float_as_uint(As[st][rA][ks + tig]);
                a[mt][1] = __float_as_uint(As[st][rA + 8][ks + tig]);
                a[mt][2] = __float_as_uint(As[st][rA][ks + tig + 4]);
                a[mt][3] = __float_as_uint(As[st][rA + 8][ks + tig + 4]);
            }
            uint32_t bf[NT][2];
#pragma unroll
            for (int nt = 0; nt < NT; nt++) {
                int cB = wc * WCW + nt * 8 + gid;
                bf[nt][0] = __float_as_uint(Bs[st][ks + tig][cB]);
                bf[nt][1] = __float_as_uint(Bs[st][ks + tig + 4][cB]);
            }
#pragma unroll
            for (int mt = 0; mt < 2; mt++)
#pragma unroll
                for (int nt = 0; nt < NT; nt++)
                    mma_tf32(c[mt][nt], a[mt], bf[nt]);
        }
    }

    // ---- epilogue ----
#pragma unroll
    for (int mt = 0; mt < 2; mt++) {
        int r0 = rowBase + wr * 32 + mt * 16 + gid;
#pragma unroll
        for (int nt = 0; nt < NT; nt++) {
            int col = colBase + wc * WCW + nt * 8 + tig * 2;
            float v0 = c[mt][nt][0], v1 = c[mt][nt][1];
            float v2 = c[mt][nt][2], v3 = c[mt][nt][3];
            if (MODE == 0) {
                float b0 = bias[col], b1 = bias[col + 1];
                size_t o0 = (size_t)r0 * G4 + col;
                size_t o1 = (size_t)(r0 + 8) * G4 + col;
                g_Xpre[o0] = v0 + b0;  g_Xpre[o0 + 1] = v1 + b1;
                g_Xpre[o1] = v2 + b0;  g_Xpre[o1 + 1] = v3 + b1;
            } else if (MODE == 1) {
                if (col < VOC) {
                    float b0 = bias[col];
                    g_logits[(size_t)r0 * VOC + col]       = v0 + b0;
                    g_logits[(size_t)(r0 + 8) * VOC + col] = v2 + b0;
                }
                if (col + 1 < VOC) {
                    float b1 = bias[col + 1];
                    g_logits[(size_t)r0 * VOC + col + 1]       = v1 + b1;
                    g_logits[(size_t)(r0 + 8) * VOC + col + 1] = v3 + b1;
                }
            } else if (MODE == 2) {
                size_t x0 = ((size_t)r0 * T + tstep) * G4 + col;
                size_t x1 = ((size_t)(r0 + 8) * T + tstep) * G4 + col;
                g_gates[r0 * G4 + col]           = v0 + g_Xpre[x0];
                g_gates[r0 * G4 + col + 1]       = v1 + g_Xpre[x0 + 1];
                g_gates[(r0 + 8) * G4 + col]     = v2 + g_Xpre[x1];
                g_gates[(r0 + 8) * G4 + col + 1] = v3 + g_Xpre[x1 + 1];
            } else {
                int n0 = r0 >> 4, p0 = r0 & 15;
                int n1 = (r0 + 8) >> 4, p1 = (r0 + 8) & 15;
                float b0 = bias[col], b1 = bias[col + 1];
                g_Aflat[n0 * (HD * 16) + col * 16 + p0]       = v0 + b0;
                g_Aflat[n0 * (HD * 16) + (col + 1) * 16 + p0] = v1 + b1;
                g_Aflat[n1 * (HD * 16) + col * 16 + p1]       = v2 + b0;
                g_Aflat[n1 * (HD * 16) + (col + 1) * 16 + p1] = v3 + b1;
            }
        }
    }
}

// ============================================================================
// attention body: 1024-thread block, h in smem. Writes tf32 attn into g_hA.
// ============================================================================
__device__ __forceinline__ void attn_body(int n, const float* sh_h, float* sh_s, int tid) {
    int w = tid >> 5, lane = tid & 31;
    const float* A = &g_Aflat[n * HD * 16];
    if (w < 16) {
        float s = 0.f;
        for (int h = lane; h < HD; h += 32) s += sh_h[h] * A[h * 16 + w];
#pragma unroll
        for (int o = 16; o > 0; o >>= 1) s += __shfl_down_sync(0xffffffffu, s, o);
        if (lane == 0) sh_s[w] = s * 0.03125f;   // 1/sqrt(1024)
    }
    __syncthreads();
    if (tid < 32) {
        float v = (lane < 16) ? sh_s[lane] : -INFINITY;
        float m = v;
#pragma unroll
        for (int o = 16; o > 0; o >>= 1) m = fmaxf(m, __shfl_xor_sync(0xffffffffu, m, o));
        float e = (lane < 16) ? __expf(v - m) : 0.f;
        float sum = e;
#pragma unroll
        for (int o = 16; o > 0; o >>= 1) sum += __shfl_xor_sync(0xffffffffu, sum, o);
        if (lane < 16) sh_s[lane] = e / sum;
    }
    __syncthreads();
    const float* ap = &A[tid * 16];
    float r = 0.f;
#pragma unroll
    for (int p = 0; p < 16; p++) r += ap[p] * sh_s[p];
    g_hA[n * 2 * HD + HD + tid] = tfv(r);
}

// h0 = c0 = mean_p A_flat, then attention for step 0. Block = sample n, 1024 thr.
__global__ void h0_attn_kernel() {
    int n = blockIdx.x;
    int tid = threadIdx.x;
    __shared__ float sh_h[HD];
    __shared__ float sh_s[16];
    const float* a = &g_Aflat[(n * HD + tid) * 16];
    float s = 0.f;
#pragma unroll
    for (int p = 0; p < 16; p++) s += a[p];
    s *= (1.0f / 16.0f);
    g_c[n * HD + tid] = s;
    g_hA[n * 2 * HD + tid] = tfv(s);
    sh_h[tid] = s;
    __syncthreads();
    attn_body(n, sh_h, sh_s, tid);
}

__device__ __forceinline__ float sigf(float x) { return 1.0f / (1.0f + __expf(-x)); }

// LSTM elementwise fused with next step's attention. Block = sample n, 1024 thr.
__global__ void lstm_attn_kernel(int t, int doAttn) {
    int n = blockIdx.x;
    int tid = threadIdx.x;
    __shared__ float sh_h[HD];
    __shared__ float sh_s[16];

    const float* gr = &g_gates[n * G4];
    float gi = gr[tid], gf = gr[tid + HD], go = gr[tid + 2 * HD], gg = gr[tid + 3 * HD];
    float c = sigf(gf) * g_c[n * HD + tid] + sigf(gi) * tanhf(gg);
    float hh = sigf(go) * tanhf(c);
    g_c[n * HD + tid] = c;
    g_hA[n * 2 * HD + tid] = tfv(hh);
    g_hsT[((size_t)t * Nn + n) * HD + tid] = tfv(hh);

    if (doAttn) {
        sh_h[tid] = hh;
        __syncthreads();
        attn_body(n, sh_h, sh_s, tid);
    }
}

// loss: per-row logsumexp + masked NLL accumulated into out[0]
__global__ void loss_kernel(const int* __restrict__ captions, float* out) {
    int r = blockIdx.x;               // r = t*N + n
    __shared__ float red[256];
    const float* row = &g_logits[(size_t)r * VOC];
    int tid = threadIdx.x;

    float m = -INFINITY;
    for (int v = tid; v < VOC; v += 256) m = fmaxf(m, row[v]);
    red[tid] = m;
    __syncthreads();
    for (int s = 128; s > 0; s >>= 1) {
        if (tid < s) red[tid] = fmaxf(red[tid], red[tid + s]);
        __syncthreads();
    }
    float mx = red[0];
    __syncthreads();

    float se = 0.f;
    for (int v = tid; v < VOC; v += 256) se += expf(row[v] - mx);
    red[tid] = se;
    __syncthreads();
    for (int s = 128; s > 0; s >>= 1) {
        if (tid < s) red[tid] += red[tid + s];
        __syncthreads();
    }

    if (tid == 0) {
        int t = r / Nn, n = r % Nn;
        int tgt = captions[n * TCAP + t + 1];
        if (tgt != 0) {
            float nll = logf(red[0]) + mx - row[tgt];
            atomicAdd(out, nll * (1.0f / Nn));
        }
    }
}

// ============================================================================
extern "C" void kernel_launch(void* const* d_in, const int* in_sizes, int n_in,
                              void* d_out, int out_size) {
    const float* images   = (const float*)d_in[0];
    const int*   captions = (const int*)  d_in[1];
    const float* W_embed  = (const float*)d_in[2];
    const float* W_proj   = (const float*)d_in[3];
    const float* b_proj   = (const float*)d_in[4];
    const float* Wx       = (const float*)d_in[5];
    const float* Wh       = (const float*)d_in[6];
    const float* Wattn    = (const float*)d_in[7];
    const float* b        = (const float*)d_in[8];
    const float* W_vocab  = (const float*)d_in[9];
    const float* b_vocab  = (const float*)d_in[10];
    float* out = (float*)d_out;

    zero_kernel<<<1, 32>>>(out);
    cvt_weights<<<(N_CVT + 255) / 256, 256>>>(W_embed, Wx, Wh, Wattn, W_vocab, W_proj);
    imgT_kernel<<<Nn, 256>>>(images);

    // proj: 2048 x 1024, K=1280
    gemm_tc<3><<<dim3(HD / 64, 2048 / 128), 256>>>(b_proj, nullptr, 0);
    h0_attn_kernel<<<Nn, 1024>>>();
    // Xpre: 3840 x 4096, K=512
    gemm_tc<0><<<dim3(G4 / 64, (Nn * T) / 128), 256>>>(b, captions, 0);

    for (int t = 0; t < T; t++) {
        // gates: 128 x 4096, K=2048, 128 CTAs
        gemm_tc<2><<<dim3(G4 / 32, 1), 256>>>(nullptr, nullptr, t);
        lstm_attn_kernel<<<Nn, 1024>>>(t, t < T - 1);
    }

    // logits: 3840 x 10000, K=1024
    gemm_tc<1><<<dim3((VOC + 63) / 64, (Nn * T) / 128), 256>>>(b_vocab, nullptr, 0);
    loss_kernel<<<T * Nn, 256>>>(captions, out);
}

// round 9
// speedup vs baseline: 2.5323x; 1.1150x over previous
#include <cuda_runtime.h>
#include <cuda_bf16.h>
#include <math.h>
#include <stdint.h>

#define Nn   128
#define TCAP 31
#define T    30
#define CIN  1280
#define WD   512
#define HD   1024
#define VOC  10000
#define G4   4096   // 4*HD

// ---------------- static device scratch (no runtime allocation) -------------
__device__ __align__(16) float g_embT[VOC * WD];            // tf32 bits
__device__ __align__(16) float g_WxT[WD * G4];
__device__ __align__(16) float g_WhA[2 * HD * G4];          // [Wh; Wattn]
__device__ __align__(16) float g_WpT[CIN * HD];
__device__ __align__(16) unsigned g_WvP[(size_t)(HD / 2) * VOC]; // bf16 k-pairs
__device__ __align__(16) float g_imgT[2048 * CIN];          // images transposed, tf32
// activations
__device__ __align__(16) float g_hA[Nn * 2 * HD];           // [h | attn] tf32
__device__ __align__(16) unsigned g_hsB[(size_t)T * Nn * HD / 2]; // hs bf16 pairs, rows (t*N+n)
__device__ float g_c[Nn * HD];
__device__ float g_Aflat[Nn * HD * 16];                     // fp32 A_flat[n,h,p]
__device__ __align__(16) float g_Xpre[(size_t)Nn * T * G4]; // fp32 rows (n*T+t)
__device__ float g_gates[Nn * G4];
__device__ float g_logits[(size_t)T * Nn * VOC];

// ---------------------------------------------------------------------------
__global__ void zero_kernel(float* out) {
    if (threadIdx.x == 0) out[0] = 0.0f;
}

__device__ __forceinline__ uint32_t f2tf32(float f) {
    uint32_t u;
    asm("cvt.rna.tf32.f32 %0, %1;" : "=r"(u) : "f"(f));
    return u;
}
__device__ __forceinline__ float tfv(float f) { return __uint_as_float(f2tf32(f)); }

__device__ __forceinline__ void mma_tf32(float c[4], const uint32_t a[4], const uint32_t b[2]) {
    asm volatile(
        "mma.sync.aligned.m16n8k8.row.col.f32.tf32.tf32.f32 "
        "{%0,%1,%2,%3}, {%4,%5,%6,%7}, {%8,%9}, {%0,%1,%2,%3};"
        : "+f"(c[0]), "+f"(c[1]), "+f"(c[2]), "+f"(c[3])
        : "r"(a[0]), "r"(a[1]), "r"(a[2]), "r"(a[3]), "r"(b[0]), "r"(b[1]));
}
__device__ __forceinline__ void mma_bf16(float c[4], const uint32_t a[4], const uint32_t b[2]) {
    asm volatile(
        "mma.sync.aligned.m16n8k16.row.col.f32.bf16.bf16.f32 "
        "{%0,%1,%2,%3}, {%4,%5,%6,%7}, {%8,%9}, {%0,%1,%2,%3};"
        : "+f"(c[0]), "+f"(c[1]), "+f"(c[2]), "+f"(c[3])
        : "r"(a[0]), "r"(a[1]), "r"(a[2]), "r"(a[3]), "r"(b[0]), "r"(b[1]));
}

__device__ __forceinline__ uint32_t smaddr(const void* p) {
    return (uint32_t)__cvta_generic_to_shared(p);
}
__device__ __forceinline__ void cpa16(uint32_t d, const void* s, int sz) {
    asm volatile("cp.async.cg.shared.global [%0], [%1], 16, %2;" :: "r"(d), "l"(s), "r"(sz));
}

// ============================================================================
// One-time per-launch conversions
// ============================================================================
#define N_EMB  (VOC * WD)
#define N_WX   (WD * G4)
#define N_WH   (HD * G4)
#define N_WP   (CIN * HD)
#define N_CVT  (N_EMB + N_WX + 2 * N_WH + N_WP)

__global__ void cvt_weights(const float* __restrict__ We, const float* __restrict__ Wx,
                            const float* __restrict__ Wh, const float* __restrict__ Wa,
                            const float* __restrict__ Wp) {
    int i = blockIdx.x * blockDim.x + threadIdx.x;
    if (i >= N_CVT) return;
    if (i < N_EMB) { g_embT[i] = tfv(We[i]); return; }
    i -= N_EMB;
    if (i < N_WX) { g_WxT[i] = tfv(Wx[i]); return; }
    i -= N_WX;
    if (i < N_WH) { g_WhA[i] = tfv(Wh[i]); return; }
    i -= N_WH;
    if (i < N_WH) { g_WhA[N_WH + i] = tfv(Wa[i]); return; }
    i -= N_WH;
    g_WpT[i] = tfv(Wp[i]);
}

// W_vocab [k][n] -> bf16 k-pair packed [k/2][n]
__global__ void pack_wv(const float* __restrict__ Wv) {
    int n = blockIdx.x * blockDim.x + threadIdx.x;
    int k2 = blockIdx.y;
    if (n < VOC) {
        unsigned lo = __bfloat16_as_ushort(__float2bfloat16(Wv[(size_t)(2 * k2) * VOC + n]));
        unsigned hi = __bfloat16_as_ushort(__float2bfloat16(Wv[(size_t)(2 * k2 + 1) * VOC + n]));
        g_WvP[(size_t)k2 * VOC + n] = lo | (hi << 16);
    }
}

// images [n, c, p] -> imgT [(n*16+p), c] tf32, smem-tiled transpose. Block = n.
__global__ void imgT_kernel(const float* __restrict__ img) {
    __shared__ float tile[256][17];
    int n = blockIdx.x;
    for (int c0 = 0; c0 < CIN; c0 += 256) {
        for (int idx = threadIdx.x; idx < 256 * 16; idx += blockDim.x) {
            int cc = idx >> 4, p = idx & 15;
            tile[cc][p] = img[(size_t)n * CIN * 16 + (c0 + cc) * 16 + p];
        }
        __syncthreads();
        for (int idx = threadIdx.x; idx < 256 * 16; idx += blockDim.x) {
            int p = idx >> 8, cc = idx & 255;
            g_imgT[(size_t)(n * 16 + p) * CIN + c0 + cc] = tfv(tile[cc][p]);
        }
        __syncthreads();
    }
}

// ============================================================================
// tf32 GEMM, cp.async 3-stage. BM=128, BK=16. BN=128 (modes 0,3) / 32 (mode 2).
// MODE 0: Xpre  = gather(embT,cap) @ WxT + b       (3840 x 4096, K=512)
// MODE 2: gates = hA @ WhA + Xpre[:,t]             (128 x 4096, K=2048)
// MODE 3: Aflat = imgT @ WpT + b_proj (scatter)    (2048 x 1024, K=1280)
// ============================================================================
template<int MODE>
__global__ void __launch_bounds__(256)
gemm_tf32(const float* __restrict__ bias, const int* __restrict__ captions, int tstep) {
    constexpr int BM = 128, BK = 16;
    constexpr int BN  = (MODE == 2) ? 32 : 128;
    constexpr int NT  = BN / 16;
    constexpr int WCW = BN / 2;
    constexpr int KD  = (MODE == 0) ? WD : (MODE == 2) ? 2 * HD : CIN;
    constexpr int LDB = (MODE == 3) ? HD : G4;
    constexpr int NIT = KD / BK;
    constexpr int AS = 20, BS = BN + 8;

    __shared__ __align__(16) float As[3][BM][AS];
    __shared__ __align__(16) float Bs[3][BK][BS];

    const float* Ab = (MODE == 0) ? g_embT : (MODE == 2) ? g_hA : g_imgT;
    const float* Bb = (MODE == 0) ? g_WxT  : (MODE == 2) ? g_WhA : g_WpT;

    const int tid = threadIdx.x;
    const int rowBase = blockIdx.y * BM;
    const int colBase = blockIdx.x * BN;
    const int wid = tid >> 5, lane = tid & 31;
    const int gid = lane >> 2, tig = lane & 3;
    const int wr = wid & 3, wc = wid >> 2;

    const int ar = tid >> 1, ak = (tid & 1) * 8;
    const float* aRow;
    if (MODE == 0) {
        int r = rowBase + ar;
        aRow = Ab + (size_t)captions[(r / T) * TCAP + (r % T)] * WD;
    } else {
        aRow = Ab + (size_t)(rowBase + ar) * KD;
    }
    // B loader layout
    const int bk = (BN == 128) ? (tid >> 4) : (tid >> 3);
    const int bc = (BN == 128) ? ((tid & 15) * 8) : ((tid & 7) * 4);
    const bool bact = (BN == 128) || (tid < 128);

    auto issue = [&](int it) {
        int st = it % 3;
        int k0 = it * BK;
        uint32_t ad = smaddr(&As[st][ar][ak]);
        const float* as = aRow + k0 + ak;
        cpa16(ad, as, 16);
        cpa16(ad + 16, as + 4, 16);
        if (bact) {
            uint32_t bd = smaddr(&Bs[st][bk][bc]);
            const float* bs = Bb + (size_t)(k0 + bk) * LDB + colBase + bc;
            cpa16(bd, bs, 16);
            if (BN == 128) cpa16(bd + 16, bs + 4, 16);
        }
        asm volatile("cp.async.commit_group;");
    };

    float c[2][NT][4] = {};
    issue(0);
    issue(1);

    for (int it = 0; it < NIT; ++it) {
        asm volatile("cp.async.wait_group 1;");
        __syncthreads();
        if (it + 2 < NIT) issue(it + 2);
        int st = it % 3;
#pragma unroll
        for (int ks = 0; ks < BK; ks += 8) {
            uint32_t a[2][4];
#pragma unroll
            for (int mt = 0; mt < 2; mt++) {
                int rA = wr * 32 + mt * 16 + gid;
                a[mt][0] = __float_as_uint(As[st][rA][ks + tig]);
                a[mt][1] = __float_as_uint(As[st][rA + 8][ks + tig]);
                a[mt][2] = __float_as_uint(As[st][rA][ks + tig + 4]);
                a[mt][3] = __float_as_uint(As[st][rA + 8][ks + tig + 4]);
            }
            uint32_t bf[NT][2];
#pragma unroll
            for (int nt = 0; nt < NT; nt++) {
                int cB = wc * WCW + nt * 8 + gid;
                bf[nt][0] = __float_as_uint(Bs[st][ks + tig][cB]);
                bf[nt][1] = __float_as_uint(Bs[st][ks + tig + 4][cB]);
            }
#pragma unroll
            for (int mt = 0; mt < 2; mt++)
#pragma unroll
                for (int nt = 0; nt < NT; nt++)
                    mma_tf32(c[mt][nt], a[mt], bf[nt]);
        }
        __syncthreads();
    }

    // ---- epilogue ----
#pragma unroll
    for (int mt = 0; mt < 2; mt++) {
        int r0 = rowBase + wr * 32 + mt * 16 + gid;
#pragma unroll
        for (int nt = 0; nt < NT; nt++) {
            int col = colBase + wc * WCW + nt * 8 + tig * 2;
            float v0 = c[mt][nt][0], v1 = c[mt][nt][1];
            float v2 = c[mt][nt][2], v3 = c[mt][nt][3];
            if (MODE == 0) {
                float b0 = bias[col], b1 = bias[col + 1];
                size_t o0 = (size_t)r0 * G4 + col;
                size_t o1 = (size_t)(r0 + 8) * G4 + col;
                g_Xpre[o0] = v0 + b0;  g_Xpre[o0 + 1] = v1 + b1;
                g_Xpre[o1] = v2 + b0;  g_Xpre[o1 + 1] = v3 + b1;
            } else if (MODE == 2) {
                size_t x0 = ((size_t)r0 * T + tstep) * G4 + col;
                size_t x1 = ((size_t)(r0 + 8) * T + tstep) * G4 + col;
                g_gates[r0 * G4 + col]           = v0 + g_Xpre[x0];
                g_gates[r0 * G4 + col + 1]       = v1 + g_Xpre[x0 + 1];
                g_gates[(r0 + 8) * G4 + col]     = v2 + g_Xpre[x1];
                g_gates[(r0 + 8) * G4 + col + 1] = v3 + g_Xpre[x1 + 1];
            } else {
                int n0 = r0 >> 4, p0 = r0 & 15;
                int n1 = (r0 + 8) >> 4, p1 = (r0 + 8) & 15;
                float b0 = bias[col], b1 = bias[col + 1];
                g_Aflat[n0 * (HD * 16) + col * 16 + p0]       = v0 + b0;
                g_Aflat[n0 * (HD * 16) + (col + 1) * 16 + p0] = v1 + b1;
                g_Aflat[n1 * (HD * 16) + col * 16 + p1]       = v2 + b0;
                g_Aflat[n1 * (HD * 16) + (col + 1) * 16 + p1] = v3 + b1;
            }
        }
    }
}

// ============================================================================
// bf16 logits GEMM: logits = hsB @ WvP + b_vocab   (3840 x 10000, K=1024)
// BM=128, BN=128, BK=32 bf16 (16 uint32 pair-rows), m16n8k16, fp32 accum.
// ============================================================================
__global__ void __launch_bounds__(256)
gemm_bf16_logits(const float* __restrict__ bias) {
    constexpr int BM = 128, BN = 128, BKP = 16;   // BKP = k-pairs per tile (K=32)
    constexpr int NT = 8, WCW = 64;
    constexpr int KP = HD / 2;                     // 512 pair-rows total
    constexpr int NIT = KP / BKP;                  // 32
    constexpr int AS = 20, BS = BN + 8;

    __shared__ __align__(16) uint32_t As[3][BM][AS];
    __shared__ __align__(16) uint32_t Bs[3][BKP][BS];

    const int tid = threadIdx.x;
    const int rowBase = blockIdx.y * BM;
    const int colBase = blockIdx.x * BN;
    const int wid = tid >> 5, lane = tid & 31;
    const int gid = lane >> 2, tig = lane & 3;
    const int wr = wid & 3, wc = wid >> 2;

    const int ar = tid >> 1, ak = (tid & 1) * 8;
    const unsigned* aRow = g_hsB + (size_t)(rowBase + ar) * KP;
    const int bk = tid >> 4, bc = (tid & 15) * 8;

    auto issue = [&](int it) {
        int st = it % 3;
        int kp = it * BKP;
        uint32_t ad = smaddr(&As[st][ar][ak]);
        const unsigned* as = aRow + kp + ak;
        cpa16(ad, as, 16);
        cpa16(ad + 16, as + 4, 16);
        uint32_t bd = smaddr(&Bs[st][bk][bc]);
        const unsigned* bs = g_WvP + (size_t)(kp + bk) * VOC + colBase + bc;
        cpa16(bd, bs, (colBase + bc + 4 <= VOC) ? 16 : 0);
        cpa16(bd + 16, bs + 4, (colBase + bc + 8 <= VOC) ? 16 : 0);
        asm volatile("cp.async.commit_group;");
    };

    float c[2][NT][4] = {};
    issue(0);
    issue(1);

    for (int it = 0; it < NIT; ++it) {
        asm volatile("cp.async.wait_group 1;");
        __syncthreads();
        if (it + 2 < NIT) issue(it + 2);
        int st = it % 3;
#pragma unroll
        for (int ks = 0; ks < BKP; ks += 8) {
            uint32_t a[2][4];
#pragma unroll
            for (int mt = 0; mt < 2; mt++) {
                int rA = wr * 32 + mt * 16 + gid;
                a[mt][0] = As[st][rA][ks + tig];
                a[mt][1] = As[st][rA + 8][ks + tig];
                a[mt][2] = As[st][rA][ks + tig + 4];
                a[mt][3] = As[st][rA + 8][ks + tig + 4];
            }
            uint32_t bf[NT][2];
#pragma unroll
            for (int nt = 0; nt < NT; nt++) {
                int cB = wc * WCW + nt * 8 + gid;
                bf[nt][0] = Bs[st][ks + tig][cB];
                bf[nt][1] = Bs[st][ks + tig + 4][cB];
            }
#pragma unroll
            for (int mt = 0; mt < 2; mt++)
#pragma unroll
                for (int nt = 0; nt < NT; nt++)
                    mma_bf16(c[mt][nt], a[mt], bf[nt]);
        }
        __syncthreads();
    }

#pragma unroll
    for (int mt = 0; mt < 2; mt++) {
        int r0 = rowBase + wr * 32 + mt * 16 + gid;
#pragma unroll
        for (int nt = 0; nt < NT; nt++) {
            int col = colBase + wc * WCW + nt * 8 + tig * 2;
            if (col < VOC) {
                float b0 = bias[col];
                g_logits[(size_t)r0 * VOC + col]       = c[mt][nt][0] + b0;
                g_logits[(size_t)(r0 + 8) * VOC + col] = c[mt][nt][2] + b0;
            }
            if (col + 1 < VOC) {
                float b1 = bias[col + 1];
                g_logits[(size_t)r0 * VOC + col + 1]       = c[mt][nt][1] + b1;
                g_logits[(size_t)(r0 + 8) * VOC + col + 1] = c[mt][nt][3] + b1;
            }
        }
    }
}

// ============================================================================
// attention body: 1024-thread block, h in smem. Writes tf32 attn into g_hA.
// ============================================================================
__device__ __forceinline__ void attn_body(int n, const float* sh_h, float* sh_s, int tid) {
    int w = tid >> 5, lane = tid & 31;
    const float* A = &g_Aflat[n * HD * 16];
    if (w < 16) {
        float s = 0.f;
        for (int h = lane; h < HD; h += 32) s += sh_h[h] * A[h * 16 + w];
#pragma unroll
        for (int o = 16; o > 0; o >>= 1) s += __shfl_down_sync(0xffffffffu, s, o);
        if (lane == 0) sh_s[w] = s * 0.03125f;   // 1/sqrt(1024)
    }
    __syncthreads();
    if (tid < 32) {
        float v = (lane < 16) ? sh_s[lane] : -INFINITY;
        float m = v;
#pragma unroll
        for (int o = 16; o > 0; o >>= 1) m = fmaxf(m, __shfl_xor_sync(0xffffffffu, m, o));
        float e = (lane < 16) ? __expf(v - m) : 0.f;
        float sum = e;
#pragma unroll
        for (int o = 16; o > 0; o >>= 1) sum += __shfl_xor_sync(0xffffffffu, sum, o);
        if (lane < 16) sh_s[lane] = e / sum;
    }
    __syncthreads();
    const float* ap = &A[tid * 16];
    float r = 0.f;
#pragma unroll
    for (int p = 0; p < 16; p++) r += ap[p] * sh_s[p];
    g_hA[n * 2 * HD + HD + tid] = tfv(r);
}

__global__ void h0_attn_kernel() {
    int n = blockIdx.x;
    int tid = threadIdx.x;
    __shared__ float sh_h[HD];
    __shared__ float sh_s[16];
    const float* a = &g_Aflat[(n * HD + tid) * 16];
    float s = 0.f;
#pragma unroll
    for (int p = 0; p < 16; p++) s += a[p];
    s *= (1.0f / 16.0f);
    g_c[n * HD + tid] = s;
    g_hA[n * 2 * HD + tid] = tfv(s);
    sh_h[tid] = s;
    __syncthreads();
    attn_body(n, sh_h, sh_s, tid);
}

__device__ __forceinline__ float sigf(float x) { return 1.0f / (1.0f + __expf(-x)); }

// LSTM elementwise fused with next step's attention. Block = sample n, 1024 thr.
__global__ void lstm_attn_kernel(int t, int doAttn) {
    int n = blockIdx.x;
    int tid = threadIdx.x;
    __shared__ float sh_h[HD];
    __shared__ float sh_s[16];

    const float* gr = &g_gates[n * G4];
    float gi = gr[tid], gf = gr[tid + HD], go = gr[tid + 2 * HD], gg = gr[tid + 3 * HD];
    float c = sigf(gf) * g_c[n * HD + tid] + sigf(gi) * tanhf(gg);
    float hh = sigf(go) * tanhf(c);
    g_c[n * HD + tid] = c;
    g_hA[n * 2 * HD + tid] = tfv(hh);
    ((__nv_bfloat16*)g_hsB)[((size_t)t * Nn + n) * HD + tid] = __float2bfloat16(hh);

    if (doAttn) {
        sh_h[tid] = hh;
        __syncthreads();
        attn_body(n, sh_h, sh_s, tid);
    }
}

// loss: per-row logsumexp + masked NLL accumulated into out[0]
__global__ void loss_kernel(const int* __restrict__ captions, float* out) {
    int r = blockIdx.x;               // r = t*N + n
    __shared__ float red[256];
    const float* row = &g_logits[(size_t)r * VOC];
    int tid = threadIdx.x;

    float m = -INFINITY;
    for (int v = tid; v < VOC; v += 256) m = fmaxf(m, row[v]);
    red[tid] = m;
    __syncthreads();
    for (int s = 128; s > 0; s >>= 1) {
        if (tid < s) red[tid] = fmaxf(red[tid], red[tid + s]);
        __syncthreads();
    }
    float mx = red[0];
    __syncthreads();

    float se = 0.f;
    for (int v = tid; v < VOC; v += 256) se += expf(row[v] - mx);
    red[tid] = se;
    __syncthreads();
    for (int s = 128; s > 0; s >>= 1) {
        if (tid < s) red[tid] += red[tid + s];
        __syncthreads();
    }

    if (tid == 0) {
        int t = r / Nn, n = r % Nn;
        int tgt = captions[n * TCAP + t + 1];
        if (tgt != 0) {
            float nll = logf(red[0]) + mx - row[tgt];
            atomicAdd(out, nll * (1.0f / Nn));
        }
    }
}

// ============================================================================
extern "C" void kernel_launch(void* const* d_in, const int* in_sizes, int n_in,
                              void* d_out, int out_size) {
    const float* images   = (const float*)d_in[0];
    const int*   captions = (const int*)  d_in[1];
    const float* W_embed  = (const float*)d_in[2];
    const float* W_proj   = (const float*)d_in[3];
    const float* b_proj   = (const float*)d_in[4];
    const float* Wx       = (const float*)d_in[5];
    const float* Wh       = (const float*)d_in[6];
    const float* Wattn    = (const float*)d_in[7];
    const float* b        = (const float*)d_in[8];
    const float* W_vocab  = (const float*)d_in[9];
    const float* b_vocab  = (const float*)d_in[10];
    float* out = (float*)d_out;

    zero_kernel<<<1, 32>>>(out);
    cvt_weights<<<(N_CVT + 255) / 256, 256>>>(W_embed, Wx, Wh, Wattn, W_proj);
    pack_wv<<<dim3((VOC + 255) / 256, HD / 2), 256>>>(W_vocab);
    imgT_kernel<<<Nn, 256>>>(images);

    // proj: 2048 x 1024, K=1280
    gemm_tf32<3><<<dim3(HD / 128, 2048 / 128), 256>>>(b_proj, nullptr, 0);
    h0_attn_kernel<<<Nn, 1024>>>();
    // Xpre: 3840 x 4096, K=512
    gemm_tf32<0><<<dim3(G4 / 128, (Nn * T) / 128), 256>>>(b, captions, 0);

    for (int t = 0; t < T; t++) {
        // gates: 128 x 4096, K=2048, 128 CTAs
        gemm_tf32<2><<<dim3(G4 / 32, 1), 256>>>(nullptr, nullptr, t);
        lstm_attn_kernel<<<Nn, 1024>>>(t, t < T - 1);
    }

    // logits: 3840 x 10000, K=1024, bf16
    gemm_bf16_logits<<<dim3((VOC + 127) / 128, (Nn * T) / 128), 256>>>(b_vocab);
    loss_kernel<<<T * Nn, 256>>>(captions, out);
}